// round 17
// baseline (speedup 1.0000x reference)
#include <cuda_runtime.h>
#include <cstdint>

#define FM 0xffffffffu
#define NW 32
#define INFV 1000000000.0f
#define KMASK6 0xFFFFFFC0u  // key: high 26 bits value, bit5 matched-flag, low 5 lane

// packed f32x2 helpers (sm_103a dual-fp32 pipe)
#define PK2(dst, lo, hi) \
    asm("mov.b64 %0, {%1, %2};" : "=l"(dst) : "f"(lo), "f"(hi))
#define UPK2(lo, hi, src) \
    asm("mov.b64 {%0, %1}, %2;" : "=f"(lo), "=f"(hi) : "l"(src))
#define ADD2(d, a, b) \
    asm("add.rn.f32x2 %0, %1, %2;" : "=l"(d) : "l"(a), "l"(b))
#define MUL2(d, a, b) \
    asm("mul.rn.f32x2 %0, %1, %2;" : "=l"(d) : "l"(a), "l"(b))
#define FMA2(d, a, b, c) \
    asm("fma.rn.f32x2 %0, %1, %2, %3;" : "=l"(d) : "l"(a), "l"(b), "l"(c))

struct Feat {
    float cx, cy, area, sr, ar, bx, by, prob;
};

__device__ __forceinline__ Feat wall_features(float sx, float sy, float ex,
                                              float ey, float w, float prob) {
    float dx = ex - sx, dy = ey - sy;
    float len = sqrtf(dx * dx + dy * dy);
    float cx = (sx + ex) * 0.5f, cy = (sy + ey) * 0.5f;
    float area = len * w;
    float smaller = fminf(w, len), bigger = fmaxf(w, len);
    float sr = (bigger > 0.0f) ? (smaller / bigger) : 0.0f;
    float px, py;
    if (len > 0.0f) {
        float s = w * 0.5f / len;
        px = dy * s;
        py = -dx * s;
    } else {
        px = 0.0f;
        py = 0.0f;
    }
    float right = fmaxf(fmaxf(sx + px, sx - px), fmaxf(ex + px, ex - px));
    float top   = fmaxf(fmaxf(sy + py, sy - py), fmaxf(ey + py, ey - py));
    float bbw = fabsf((right - cx) * 2.0f);
    float bbh = fabsf((top  - cy) * 2.0f);
    float bba = bbw * bbh;
    float ar = (bba > 0.001f) ? (area / bba) : 1.0f;
    Feat f;
    f.cx = cx; f.cy = cy; f.area = area; f.sr = sr; f.ar = ar;
    f.bx = bbw; f.by = bbh; f.prob = prob;
    return f;
}

__device__ __forceinline__ Feat load_features(const float* __restrict__ base,
                                              int b, int lane) {
    const float2* q = (const float2*)(base + (size_t)b * NW * 6 + lane * 6);
    float2 p0 = q[0], p1 = q[1], p2 = q[2];
    return wall_features(p0.x, p0.y, p1.x, p1.y, p2.x, p2.y);
}

// One warp per batch; columns (pred walls) <-> lanes.
// JV: column reduction -> kick-free free-row pass (free-preferred tie keys)
// -> SAP with M staging & predecessor-column paths, biased positive slacks.
// Fill tracks the column argmin in integer-key space (costs >= 0 so raw
// float bits are uint-ordered): 2 instr per cost instead of 3.
__global__ void __launch_bounds__(32)
floorplanet_kernel(const float* __restrict__ params_true,
                   const float* __restrict__ params_pred,
                   float* __restrict__ out) {
    __shared__ float C[NW * NW];
    __shared__ float M[NW * NW];
    __shared__ float G[16 * 16];   // G[pair*16 + feat*2 + half]
    __shared__ int c4r_sh[NW];

    const int b = blockIdx.x;
    const int lane = threadIdx.x;

    Feat ft = load_features(params_true, b, lane);
    Feat fp = load_features(params_pred, b, lane);

    // Stage row features pair-interleaved: pair ip = lane>>1, half = lane&1.
    {
        float* g = G + (lane >> 1) * 16 + (lane & 1);
        g[0]  = ft.cx;   g[2]  = ft.cy;
        g[4]  = ft.area; g[6]  = ft.sr;
        g[8]  = ft.ar;   g[10] = ft.bx;
        g[12] = ft.by;   g[14] = ft.prob;
    }
    uint64_t nx2, ny2, na2, ns2, nr2, nbx2, nby2, np2, ten2;
    PK2(nx2,  -fp.cx,   -fp.cx);
    PK2(ny2,  -fp.cy,   -fp.cy);
    PK2(na2,  -fp.area, -fp.area);
    PK2(ns2,  -fp.sr,   -fp.sr);
    PK2(nr2,  -fp.ar,   -fp.ar);
    PK2(nbx2, -fp.bx,   -fp.bx);
    PK2(nby2, -fp.by,   -fp.by);
    PK2(np2,  -fp.prob, -fp.prob);
    PK2(ten2, 10.0f, 10.0f);
    __syncwarp();

    // Fill C two rows at a time (packed f32x2); integer-key column argmin.
    unsigned ck = 0xFFFFFFFFu;   // (cost bits:27 | row:5), costs >= 0
#pragma unroll 4
    for (int ip = 0; ip < 16; ip++) {
        const uint64_t* g = (const uint64_t*)(G + ip * 16);
        uint64_t x2 = g[0], y2 = g[1], a2 = g[2], s2 = g[3];
        uint64_t r2 = g[4], bx2 = g[5], by2 = g[6], p2 = g[7];

        uint64_t d0, d1, d2, d3, d4, d5, d6, dp, pd, t, cost2;
        ADD2(d0, x2,  nx2);
        ADD2(d1, y2,  ny2);
        ADD2(d2, a2,  na2);
        ADD2(d3, s2,  ns2);
        ADD2(d4, r2,  nr2);
        ADD2(d5, bx2, nbx2);
        ADD2(d6, by2, nby2);
        ADD2(dp, p2,  np2);
        MUL2(pd, d0, d0);
        FMA2(pd, d1, d1, pd);
        FMA2(pd, d2, d2, pd);
        FMA2(pd, d3, d3, pd);
        FMA2(pd, d4, d4, pd);
        FMA2(pd, d5, d5, pd);
        FMA2(pd, d6, d6, pd);
        MUL2(t, dp, dp);
        MUL2(t, t, ten2);
        FMA2(cost2, pd, p2, t);      // 10*dp^2 + param_d * iprob

        float c0, c1;
        UPK2(c0, c1, cost2);
        C[(2 * ip) * NW + lane] = c0;
        C[(2 * ip + 1) * NW + lane] = c1;
        unsigned k0 = (__float_as_uint(c0) & ~31u) | (unsigned)(2 * ip);
        unsigned k1 = (__float_as_uint(c1) & ~31u) | (unsigned)(2 * ip + 1);
        ck = umin(ck, umin(k0, k1));
    }
    __syncwarp();

    // ---- Phase 1: column reduction. v[j]=colmin (quantized down -> reduced
    // costs stay >= 0), greedily match argmin rows.
    int am = ck & 31;
    float v = __uint_as_float(ck & ~31u), u = 0.0f;
    unsigned grp = __match_any_sync(FM, am);
    bool winner = ((__ffs(grp) - 1) == lane);
    int row4col = winner ? am : -1;
    c4r_sh[lane] = -1;
    __syncwarp();
    if (winner) c4r_sh[am] = lane;
    __syncwarp();
    int col4row = c4r_sh[lane];
    unsigned freerows = __ballot_sync(FM, col4row < 0);

    // ---- Phase 2': kick-free free-row pass with free-preferred tie keys.
    unsigned matchbit = (row4col >= 0) ? 32u : 0u;
    unsigned rem = freerows;
    while (rem) {
        const int i = __ffs(rem) - 1;
        rem &= rem - 1;
        float d = C[i * NW + lane] - v;   // >= 0 (v = colmin rounded down)
        unsigned k = (__float_as_uint(d) & KMASK6) | matchbit | (unsigned)lane;
        unsigned m = __reduce_min_sync(FM, k);
        float umin_ = __uint_as_float(m & KMASK6);
        if (lane == i) u = umin_;
        if (!(m & 32u)) {                 // free column won -> match
            int j = m & 31;
            if (lane == j) { row4col = i; matchbit = 32u; }
            if (lane == i) col4row = j;
        }
    }
    freerows = __ballot_sync(FM, col4row < 0);

    // ---- Phase 3: SAP, biased slacks (slackb = slack + 1 > 0).
    if (freerows) {
        // Branchless M staging: M[j][l] = C[row4col[j]][l]; free columns get
        // a dummy row (never read before overwrite during augmentation).
        c4r_sh[lane] = row4col;
        __syncwarp();
#pragma unroll 1
        for (int j = 0; j < NW; j++) {
            int r = c4r_sh[j];
            M[j * NW + lane] = C[(r & 31) * NW + lane];
        }
        __syncwarp();
    }

    while (freerows) {
        const int i0 = __ffs(freerows) - 1;
        freerows &= freerows - 1;

        float ur = __shfl_sync(FM, u, row4col & 31);  // u[row4col[lane]]
        float ui = __shfl_sync(FM, u, i0);
        unsigned mkey = 0xFFFFFFFFu;
        // laneor = lane | matched-flag; ~0 once selected (SC member).
        unsigned laneor = (unsigned)lane | ((row4col >= 0) ? 32u : 0u);
        float spcb = INFV;                  // set once, at selection
        int pathcol = 32;                   // predecessor column (32 == i0)
        int j = 32;                         // previous selection (sentinel)
        float minValb = 1.0f;
        float slackb = (C[i0 * NW + lane] - ui - v) + 1.0f;   // >= 1
        int sink;

        for (;;) {
            unsigned skey = (__float_as_uint(slackb) & KMASK6) | laneor;
            bool upd = skey < mkey;
            mkey = upd ? skey : mkey;
            pathcol = upd ? j : pathcol;
            unsigned om = __reduce_min_sync(FM, mkey);
            j = om & 31;
            minValb = __uint_as_float(om & KMASK6);
            if (!(om & 32u)) { sink = j; break; }   // free column: done
            if (lane == j) {                // selection: freeze spcb, retire key
                spcb = minValb;
                laneor = 0xFFFFFFFFu;
                mkey = 0xFFFFFFFFu;
            }
            float urj = __shfl_sync(FM, ur, j);     // overlaps the M LDS
            slackb = M[j * NW + lane] - ((urj - minValb) + v);
        }

        // Dual updates. SC = selected lanes; scanned rows = {i0} U matched(SC).
        // (sink is not in SC: its v-update is exactly 0 and no row maps to it.)
        unsigned SC = __ballot_sync(FM, laneor == 0xFFFFFFFFu);
        float spcb_c4r = __shfl_sync(FM, spcb, col4row & 31);
        bool inSR = (lane == i0) ||
                    ((col4row >= 0) && ((SC >> col4row) & 1u));
        if (inSR)
            u += (lane == i0) ? (minValb - 1.0f) : (minValb - spcb_c4r);
        if ((SC >> lane) & 1u) v -= minValb - spcb;

        // Augment along the predecessor-column chain; refresh M on the way.
        int jj = sink;
        for (;;) {
            int pc = __shfl_sync(FM, pathcol, jj);
            int rc = __shfl_sync(FM, row4col, pc & 31);   // old row of pc
            int pi = (pc == 32) ? i0 : rc;
            if (lane == jj) row4col = pi;
            if (lane == pi) col4row = jj;
            M[jj * NW + lane] = C[pi * NW + lane];
            if (pc == 32) break;
            jj = pc;
        }
    }

    // loss = sum_i C[i][col4row[i]]
    float c = C[lane * NW + (col4row & 31)];
#pragma unroll
    for (int off = 16; off > 0; off >>= 1)
        c += __shfl_xor_sync(FM, c, off);
    if (lane == 0) out[b] = c;
}

extern "C" void kernel_launch(void* const* d_in, const int* in_sizes, int n_in,
                              void* d_out, int out_size) {
    const float* params_true = (const float*)d_in[0];
    const float* params_pred = (const float*)d_in[1];
    float* out = (float*)d_out;
    (void)in_sizes; (void)n_in; (void)out_size;
    floorplanet_kernel<<<2048, 32>>>(params_true, params_pred, out);
}